// round 9
// baseline (speedup 1.0000x reference)
#include <cuda_runtime.h>
#include <cuda_fp16.h>
#include <stdint.h>
#include <math.h>

#define BATCH 16
#define CH    512
#define DD    4096

// ------------------- scratch (__device__ globals) -------------------
__device__ __half g_qh[BATCH * CH * DD];   // x1 fp16 [b][c][d]  (for GEMM3 B)
__device__ __half g_kh[BATCH * CH * DD];   // x2 fp16 [b][e][d]  (for GEMM2 B)
__device__ float  g_S [BATCH * CH * CH];   // scores fp32 [b][c][e]
__device__ __half g_Pa[BATCH * CH * CH];   // row softmax fp16 [b][c][e]
__device__ __half g_Mn[BATCH * CH * CH];   // col softmax fp16 [b][c][e]

// ------------------- helpers -------------------
__device__ __forceinline__ unsigned smem_u32(const void* p) {
    unsigned a;
    asm("{ .reg .u64 t; cvta.to.shared.u64 t, %1; cvt.u32.u64 %0, t; }" : "=r"(a) : "l"(p));
    return a;
}

#define CPA16(dst, src)  asm volatile("cp.async.cg.shared.global [%0], [%1], 16;" :: "r"(dst), "l"(src) : "memory")
#define CPA_COMMIT()     asm volatile("cp.async.commit_group;" ::: "memory")
#define CPA_WAITG(n)     asm volatile("cp.async.wait_group %0;" :: "n"(n) : "memory")

#define LDSM_X4(r, a) asm volatile(                                    \
    "ldmatrix.sync.aligned.m8n8.x4.shared.b16 {%0,%1,%2,%3}, [%4];"    \
    : "=r"((r)[0]), "=r"((r)[1]), "=r"((r)[2]), "=r"((r)[3]) : "r"(a))
#define LDSM_X4T(r, a) asm volatile(                                   \
    "ldmatrix.sync.aligned.m8n8.x4.trans.shared.b16 {%0,%1,%2,%3}, [%4];" \
    : "=r"((r)[0]), "=r"((r)[1]), "=r"((r)[2]), "=r"((r)[3]) : "r"(a))

__device__ __forceinline__ void mma16816(float* c, const unsigned* a,
                                         unsigned b0, unsigned b1) {
    asm volatile(
        "mma.sync.aligned.m16n8k16.row.col.f32.f16.f16.f32 "
        "{%0,%1,%2,%3}, {%4,%5,%6,%7}, {%8,%9}, {%0,%1,%2,%3};"
        : "+f"(c[0]), "+f"(c[1]), "+f"(c[2]), "+f"(c[3])
        : "r"(a[0]), "r"(a[1]), "r"(a[2]), "r"(a[3]), "r"(b0), "r"(b1));
}

// ============ Fused kernel 1: GEMM1 (fp32 in, inline cvt) + convert-cast CTAs ============
// gemm role (blockIdx.x < 256): S[b] = (1/64) * x1[b] @ x2[b]^T, M=N=512, K=4096
//   fp32 tiles via cp.async (2 stages), per-kt convert to one fp16 buffer, HMMA core.
// convert role (blockIdx.x >= 256): qh = half(x1), kh = half(x2), grid-strided.
#define G1_NCONV 1792
#define ROWF  144                        // fp32 tile row stride (128B data + 16B pad)
#define FTILE (128 * ROWF)               // 18432
#define FSTG  (2 * FTILE)                // 36864 (A + B)
#define HROW  80                         // fp16 tile row stride (64B data + 16B pad)
#define HTILE (128 * HROW)               // 10240
#define HBUF_OFF (2 * FSTG)              // 73728
#define SMF (2 * FSTG + 2 * HTILE)       // 94208

__global__ void __launch_bounds__(128, 2)
fused_g1_conv(const float* __restrict__ x1, const float* __restrict__ x2,
              __half* __restrict__ qh, __half* __restrict__ kh,
              float* __restrict__ S)
{
    extern __shared__ char smem[];
    const int tid = threadIdx.x;

    if (blockIdx.x >= 256) {
        // ---- convert role ----
        const long n4 = (long)BATCH * CH * DD / 4;
        const long stride = (long)G1_NCONV * 128;
        for (long i = (long)(blockIdx.x - 256) * 128 + tid; i < n4; i += stride) {
            float4 v1 = ((const float4*)x1)[i];
            float4 v2 = ((const float4*)x2)[i];
            __half2 h1a = __floats2half2_rn(v1.x, v1.y), h1b = __floats2half2_rn(v1.z, v1.w);
            __half2 h2a = __floats2half2_rn(v2.x, v2.y), h2b = __floats2half2_rn(v2.z, v2.w);
            uint2 o1 = { *(unsigned*)&h1a, *(unsigned*)&h1b };
            uint2 o2 = { *(unsigned*)&h2a, *(unsigned*)&h2b };
            ((uint2*)qh)[i] = o1;
            ((uint2*)kh)[i] = o2;
        }
        return;
    }

    // ---- gemm role ----
    const unsigned sb = smem_u32(smem);
    const int bz = blockIdx.x >> 4;          // batch
    const int by = (blockIdx.x >> 2) & 3;    // m block (c)
    const int bx = blockIdx.x & 3;           // n block (e)

    const int wid = tid >> 5, lane = tid & 31;
    const int wm  = wid & 1, wn = wid >> 1;  // 2x2 warps, 64x64 tiles

    const float* Ab = x1 + (long)bz * CH * DD + (long)(by * 128) * DD;
    const float* Bb = x2 + (long)bz * CH * DD + (long)(bx * 128) * DD;

    // fp32 stage loader: tile = 128 rows x 32 floats (128 B), 8 chunks/row
    auto load_f32 = [&](int kt, int s) {
        const unsigned base = sb + (unsigned)s * FSTG;
#pragma unroll
        for (int p = 0; p < 8; p++) {
            int i = tid + p * 128;
            int row = i >> 3, c4 = i & 7;
            CPA16(base + (unsigned)(row * ROWF + c4 * 16),
                  (const char*)(Ab + (long)row * DD + kt * 32) + c4 * 16);
            CPA16(base + FTILE + (unsigned)(row * ROWF + c4 * 16),
                  (const char*)(Bb + (long)row * DD + kt * 32) + c4 * 16);
        }
    };

    // fp32 stage -> fp16 buffer (A then B), 8 fp16-16B-chunks per thread
    auto cvt_stage = [&](int s) {
        char* fb = smem + (long)s * FSTG;
        char* hb = smem + HBUF_OFF;
#pragma unroll
        for (int p = 0; p < 8; p++) {
            int i = tid + p * 128;       // 0..1023
            int t = i >> 9;              // 0 = A, 1 = B
            int j = i & 511;
            int row = j >> 2, cc = j & 3;
            const float4* src = (const float4*)(fb + t * FTILE + row * ROWF + cc * 32);
            float4 v0 = src[0], v1 = src[1];
            __half2 h0 = __floats2half2_rn(v0.x, v0.y);
            __half2 h1 = __floats2half2_rn(v0.z, v0.w);
            __half2 h2 = __floats2half2_rn(v1.x, v1.y);
            __half2 h3 = __floats2half2_rn(v1.z, v1.w);
            uint4 o = { *(unsigned*)&h0, *(unsigned*)&h1, *(unsigned*)&h2, *(unsigned*)&h3 };
            *(uint4*)(hb + t * HTILE + row * HROW + cc * 16) = o;
        }
    };

    // ldmatrix lane offsets within fp16 buffers
    const unsigned a_off = (unsigned)((wm * 64 + (lane & 15)) * HROW + ((lane >> 4) & 1) * 16);
    const unsigned b_off = (unsigned)((wn * 64 + (lane & 7) + ((lane >> 4) & 1) * 8) * HROW
                                      + ((lane >> 3) & 1) * 16);
    const unsigned hA = sb + HBUF_OFF;
    const unsigned hB = sb + HBUF_OFF + HTILE;

    float acc[4][8][4];
#pragma unroll
    for (int i = 0; i < 4; i++)
#pragma unroll
        for (int j = 0; j < 8; j++)
#pragma unroll
            for (int v = 0; v < 4; v++) acc[i][j][v] = 0.f;

    const int NT = DD / 32;   // 128
    load_f32(0, 0); CPA_COMMIT();
    load_f32(1, 1); CPA_COMMIT();

    for (int kt = 0; kt < NT; kt++) {
        if (kt + 1 < NT) { CPA_WAITG(1); } else { CPA_WAITG(0); }
        __syncthreads();
        cvt_stage(kt & 1);
        __syncthreads();
        if (kt + 2 < NT) { load_f32(kt + 2, kt & 1); CPA_COMMIT(); }

#pragma unroll
        for (int ks = 0; ks < 2; ks++) {
            unsigned af[4][4], bf[4][4];
#pragma unroll
            for (int mi = 0; mi < 4; mi++)
                LDSM_X4(af[mi], hA + a_off + (unsigned)(mi * 16 * HROW + ks * 32));
#pragma unroll
            for (int nt = 0; nt < 4; nt++)
                LDSM_X4(bf[nt], hB + b_off + (unsigned)(nt * 16 * HROW + ks * 32));
#pragma unroll
            for (int mi = 0; mi < 4; mi++)
#pragma unroll
                for (int n8 = 0; n8 < 8; n8++) {
                    const unsigned* bp = bf[n8 >> 1];
                    mma16816(acc[mi][n8], af[mi],
                             bp[(n8 & 1) * 2], bp[(n8 & 1) * 2 + 1]);
                }
        }
    }

    // epilogue: S = acc / 64
    float* Cb = S + (long)bz * CH * CH + (long)(by * 128 + wm * 64) * CH + bx * 128 + wn * 64;
    const int r0 = lane >> 2, c0 = (lane & 3) * 2;
#pragma unroll
    for (int mi = 0; mi < 4; mi++) {
#pragma unroll
        for (int n8 = 0; n8 < 8; n8++) {
            float* p = Cb + (long)(mi * 16 + r0) * CH + n8 * 8 + c0;
            float2 v0 = { acc[mi][n8][0] * (1.0f / 64.0f), acc[mi][n8][1] * (1.0f / 64.0f) };
            float2 v1 = { acc[mi][n8][2] * (1.0f / 64.0f), acc[mi][n8][3] * (1.0f / 64.0f) };
            *(float2*)p = v0;
            *(float2*)(p + 8 * (long)CH) = v1;
        }
    }
}

// ------------------- HMMA fp16 GEMM (R7 config: BK=32, 4 stages) -------------------
//   ALAY 0: A row-major [M][K], non-trans ldmatrix    ALAY 1: A stored [K][M], trans
//   BLAY 0: B row-major [N][K], non-trans ldmatrix    BLAY 1: B stored [K][N], trans
#define BK      32
#define ROWMK   80
#define ROWKN   272
#define NSTAGE  4

template<int LAY> struct TileBytes { static const int v = 128 * ROWMK; };  // 10240
template<> struct TileBytes<1>     { static const int v = BK * ROWKN;  };  // 8704

template<int ALAY, int BLAY>
__global__ void __launch_bounds__(128, 2)
gemm_mma(const __half* __restrict__ A, const __half* __restrict__ B, float* __restrict__ C,
         int K, int lda, int ldb, int ldc,
         long sA, long sB, long sC, float scale)
{
    constexpr int ATB = TileBytes<ALAY>::v;
    constexpr int BTB = TileBytes<BLAY>::v;
    constexpr int STG = ATB + BTB;

    extern __shared__ char smem[];
    const unsigned sb = smem_u32(smem);

    const int tid  = threadIdx.x;
    const int wid  = tid >> 5, lane = tid & 31;
    const int wm   = wid & 1, wn = wid >> 1;

    const int m0 = blockIdx.y * 128, n0 = blockIdx.x * 128;
    const __half* Ab = A + (long)blockIdx.z * sA + (ALAY == 0 ? (long)m0 * lda : (long)m0);
    const __half* Bb = B + (long)blockIdx.z * sB + (BLAY == 0 ? (long)n0 * ldb : (long)n0);

    auto load_tile = [&](const __half* G, int ld, int kt, unsigned dstBase, int lay) {
#pragma unroll
        for (int h = 0; h < 4; h++) {
            int i = tid + h * 128;
            if (lay == 0) {
                int row = i >> 2, c = i & 3;
                CPA16(dstBase + (unsigned)(row * ROWMK + c * 16),
                      (const char*)(G + (long)row * ld + kt * BK) + c * 16);
            } else {
                int row = i >> 4, c = i & 15;
                CPA16(dstBase + (unsigned)(row * ROWKN + c * 16),
                      (const char*)(G + (long)(kt * BK + row) * ld) + c * 16);
            }
        }
    };
    auto load_stage = [&](int kt, int s) {
        const unsigned base = sb + (unsigned)s * STG;
        load_tile(Ab, lda, kt, base, ALAY);
        load_tile(Bb, ldb, kt, base + ATB, BLAY);
    };

    unsigned a_off, b_off;
    if (ALAY == 0)
        a_off = (unsigned)((wm * 64 + (lane & 15)) * ROWMK + ((lane >> 4) & 1) * 16);
    else
        a_off = (unsigned)(((lane & 7) + ((lane >> 4) & 1) * 8) * ROWKN
                           + (wm * 64 + ((lane >> 3) & 1) * 8) * 2);
    if (BLAY == 0)
        b_off = (unsigned)(ATB + (wn * 64 + (lane & 7) + ((lane >> 4) & 1) * 8) * ROWMK
                           + ((lane >> 3) & 1) * 16);
    else
        b_off = (unsigned)(ATB + ((lane & 7) + ((lane >> 3) & 1) * 8) * ROWKN
                           + (wn * 64 + ((lane >> 4) & 1) * 8) * 2);

    float acc[4][8][4];
#pragma unroll
    for (int i = 0; i < 4; i++)
#pragma unroll
        for (int j = 0; j < 8; j++)
#pragma unroll
            for (int v = 0; v < 4; v++) acc[i][j][v] = 0.f;

    const int NT = K / BK;
    load_stage(0, 0); CPA_COMMIT();
    load_stage(1, 1); CPA_COMMIT();
    load_stage(2, 2); CPA_COMMIT();

    for (int kt = 0; kt < NT; kt++) {
        CPA_WAITG(2);
        __syncthreads();
        if (kt + 3 < NT) load_stage(kt + 3, (kt + 3) & (NSTAGE - 1));
        CPA_COMMIT();

        const unsigned stg = sb + (unsigned)(kt & (NSTAGE - 1)) * STG;
#pragma unroll
        for (int ks = 0; ks < 2; ks++) {
            unsigned af[4][4], bf[4][4];
#pragma unroll
            for (int mi = 0; mi < 4; mi++) {
                if (ALAY == 0)
                    LDSM_X4(af[mi], stg + a_off + (unsigned)(mi * 16 * ROWMK + ks * 32));
                else
                    LDSM_X4T(af[mi], stg + a_off + (unsigned)(ks * 16 * ROWKN + mi * 32));
            }
#pragma unroll
            for (int nt = 0; nt < 4; nt++) {
                if (BLAY == 0)
                    LDSM_X4(bf[nt], stg + b_off + (unsigned)(nt * 16 * ROWMK + ks * 32));
                else
                    LDSM_X4T(bf[nt], stg + b_off + (unsigned)(ks * 16 * ROWKN + nt * 32));
            }
#pragma unroll
            for (int mi = 0; mi < 4; mi++)
#pragma unroll
                for (int n8 = 0; n8 < 8; n8++) {
                    const unsigned* bp = bf[n8 >> 1];
                    mma16816(acc[mi][n8], af[mi],
                             bp[(n8 & 1) * 2], bp[(n8 & 1) * 2 + 1]);
                }
        }
    }

    float* Cb = C + (long)blockIdx.z * sC
                  + (long)(m0 + wm * 64) * ldc + n0 + wn * 64;
    const int r0 = lane >> 2, c0 = (lane & 3) * 2;
#pragma unroll
    for (int mi = 0; mi < 4; mi++) {
#pragma unroll
        for (int n8 = 0; n8 < 8; n8++) {
            float* p = Cb + (long)(mi * 16 + r0) * ldc + n8 * 8 + c0;
            float2 v0 = { acc[mi][n8][0] * scale, acc[mi][n8][1] * scale };
            float2 v1 = { acc[mi][n8][2] * scale, acc[mi][n8][3] * scale };
            *(float2*)p = v0;
            *(float2*)(p + 8 * (long)ldc) = v1;
        }
    }
}

// ------------------- row softmax (fp16 out) -------------------
__global__ void row_softmax_k(const float* __restrict__ S, __half* __restrict__ P)
{
    const int b = blockIdx.y, r = blockIdx.x;
    const float* row = S + ((long)b * CH + r) * CH;
    __half* prow = P + ((long)b * CH + r) * CH;
    const int tid = threadIdx.x;   // 256

    float v0 = row[tid], v1 = row[tid + 256];
    float m = fmaxf(v0, v1);
#pragma unroll
    for (int o = 16; o > 0; o >>= 1) m = fmaxf(m, __shfl_xor_sync(0xffffffffu, m, o));

    __shared__ float red[8];
    if ((tid & 31) == 0) red[tid >> 5] = m;
    __syncthreads();
    float mall = red[0];
#pragma unroll
    for (int w = 1; w < 8; w++) mall = fmaxf(mall, red[w]);

    float e0 = expf(v0 - mall), e1 = expf(v1 - mall);
    float s = e0 + e1;
#pragma unroll
    for (int o = 16; o > 0; o >>= 1) s += __shfl_xor_sync(0xffffffffu, s, o);
    __syncthreads();
    if ((tid & 31) == 0) red[tid >> 5] = s;
    __syncthreads();
    float sall = 0.f;
#pragma unroll
    for (int w = 0; w < 8; w++) sall += red[w];

    float inv = 1.0f / sall;
    prow[tid]       = __float2half_rn(e0 * inv);
    prow[tid + 256] = __float2half_rn(e1 * inv);
}

// ------------------- col softmax, natural-layout output Mn[b][c][e] -------------------
__global__ void col_softmax_k(const float* __restrict__ S, __half* __restrict__ Mn)
{
    const int b    = blockIdx.y;
    const int tid  = threadIdx.x;      // 512
    const int lane = tid & 63;
    const int g    = tid >> 6;         // c-group 0..7
    const int e    = blockIdx.x * 64 + lane;

    const float* Sb = S + (long)b * CH * CH;
    __half* Mb = Mn + (long)b * CH * CH;

    float m = -INFINITY, s = 0.f;
    for (int c = g * 64; c < g * 64 + 64; c += 4) {
        float v0 = Sb[(long)(c + 0) * CH + e];
        float v1 = Sb[(long)(c + 1) * CH + e];
        float v2 = Sb[(long)(c + 2) * CH + e];
        float v3 = Sb[(long)(c + 3) * CH + e];
        float mn   = fmaxf(fmaxf(v0, v1), fmaxf(v2, v3));
        float mnew = fmaxf(m, mn);
        s = s * expf(m - mnew)
          + expf(v0 - mnew) + expf(v1 - mnew) + expf(v2 - mnew) + expf(v3 - mnew);
        m = mnew;
    }

    __shared__ float sm[8][64];
    __shared__ float ss[8][64];
    sm[g][lane] = m;
    ss[g][lane] = s;
    __syncthreads();

    float M = -INFINITY, Sv = 0.f;
#pragma unroll
    for (int gi = 0; gi < 8; gi++) {
        float mg = sm[gi][lane], sg = ss[gi][lane];
        float Mn2 = fmaxf(M, mg);
        Sv = Sv * expf(M - Mn2) + sg * expf(mg - Mn2);
        M = Mn2;
    }
    float inv = 1.0f / Sv;

    for (int c = g * 64; c < g * 64 + 64; c++) {
        Mb[(long)c * CH + e] = __float2half_rn(expf(Sb[(long)c * CH + e] - M) * inv);
    }
}

// ------------------- launcher -------------------
extern "C" void kernel_launch(void* const* d_in, const int* in_sizes, int n_in,
                              void* d_out, int out_size)
{
    const float* x1 = (const float*)d_in[0];
    const float* x2 = (const float*)d_in[1];
    float* outA = (float*)d_out;
    float* outB = outA + (long)BATCH * CH * DD;

    __half *qh, *kh, *Pa, *Mn;
    float *S;
    cudaGetSymbolAddress((void**)&qh, g_qh);
    cudaGetSymbolAddress((void**)&kh, g_kh);
    cudaGetSymbolAddress((void**)&S,  g_S);
    cudaGetSymbolAddress((void**)&Pa, g_Pa);
    cudaGetSymbolAddress((void**)&Mn, g_Mn);

    constexpr int SM01 = NSTAGE * (TileBytes<0>::v + TileBytes<1>::v);  // 75776
    constexpr int SM11 = NSTAGE * (TileBytes<1>::v + TileBytes<1>::v);  // 69632
    cudaFuncSetAttribute(fused_g1_conv, cudaFuncAttributeMaxDynamicSharedMemorySize, SMF);
    cudaFuncSetAttribute(gemm_mma<0, 1>, cudaFuncAttributeMaxDynamicSharedMemorySize, SM01);
    cudaFuncSetAttribute(gemm_mma<1, 1>, cudaFuncAttributeMaxDynamicSharedMemorySize, SM11);

    // 1) fused: S = (1/64) q k^T  (fp32 inputs, inline cvt)  +  qh/kh convert CTAs
    fused_g1_conv<<<256 + G1_NCONV, 128, SMF>>>(x1, x2, qh, kh, S);

    // 2) softmaxes
    row_softmax_k<<<dim3(CH, BATCH), 256>>>(S, Pa);
    col_softmax_k<<<dim3(CH / 64, BATCH), 512>>>(S, Mn);

    // 3) outA = Pa @ k            M=512 N=4096 K=512; A=Pa[M][K], B=kh[K][N]
    gemm_mma<0, 1><<<dim3(DD / 128, CH / 128, BATCH), 128, SM01>>>(
        Pa, kh, outA, CH, CH, DD, DD,
        (long)CH * CH, (long)CH * DD, (long)CH * DD, 1.0f);

    // 4) outB = M^T @ q           M=512(e) N=4096(d) K=512(c); A=Mn[K][M], B=qh[K][N]
    gemm_mma<1, 1><<<dim3(DD / 128, CH / 128, BATCH), 128, SM11>>>(
        Mn, qh, outB, CH, CH, DD, DD,
        (long)CH * CH, (long)CH * DD, (long)CH * DD, 1.0f);
}

// round 10
// speedup vs baseline: 1.3937x; 1.3937x over previous
#include <cuda_runtime.h>
#include <cuda_fp16.h>
#include <stdint.h>
#include <math.h>

#define BATCH 16
#define CH    512
#define DD    4096

// ------------------- scratch (__device__ globals) -------------------
__device__ __half g_qh[BATCH * CH * DD];   // x1 fp16 [b][c][d]
__device__ __half g_kh[BATCH * CH * DD];   // x2 fp16 [b][e][d]
__device__ float  g_S [BATCH * CH * CH];   // scores fp32 [b][c][e]
__device__ __half g_Pa[BATCH * CH * CH];   // row softmax fp16 [b][c][e]
__device__ __half g_Mn[BATCH * CH * CH];   // col softmax fp16 [b][c][e]

// ------------------- helpers -------------------
__device__ __forceinline__ unsigned smem_u32(const void* p) {
    unsigned a;
    asm("{ .reg .u64 t; cvta.to.shared.u64 t, %1; cvt.u32.u64 %0, t; }" : "=r"(a) : "l"(p));
    return a;
}

#define CPA16(dst, src)  asm volatile("cp.async.cg.shared.global [%0], [%1], 16;" :: "r"(dst), "l"(src) : "memory")
#define CPA_COMMIT()     asm volatile("cp.async.commit_group;" ::: "memory")
#define CPA_WAITG(n)     asm volatile("cp.async.wait_group %0;" :: "n"(n) : "memory")

#define LDSM_X4(r, a) asm volatile(                                    \
    "ldmatrix.sync.aligned.m8n8.x4.shared.b16 {%0,%1,%2,%3}, [%4];"    \
    : "=r"((r)[0]), "=r"((r)[1]), "=r"((r)[2]), "=r"((r)[3]) : "r"(a))
#define LDSM_X4T(r, a) asm volatile(                                   \
    "ldmatrix.sync.aligned.m8n8.x4.trans.shared.b16 {%0,%1,%2,%3}, [%4];" \
    : "=r"((r)[0]), "=r"((r)[1]), "=r"((r)[2]), "=r"((r)[3]) : "r"(a))

__device__ __forceinline__ void mma16816(float* c, const unsigned* a,
                                         unsigned b0, unsigned b1) {
    asm volatile(
        "mma.sync.aligned.m16n8k16.row.col.f32.f16.f16.f32 "
        "{%0,%1,%2,%3}, {%4,%5,%6,%7}, {%8,%9}, {%0,%1,%2,%3};"
        : "+f"(c[0]), "+f"(c[1]), "+f"(c[2]), "+f"(c[3])
        : "r"(a[0]), "r"(a[1]), "r"(a[2]), "r"(a[3]), "r"(b0), "r"(b1));
}

// ------------------- pure fp32 -> fp16 cast -------------------
__global__ void convert_cast(const float* __restrict__ x1, const float* __restrict__ x2,
                             __half* __restrict__ qh, __half* __restrict__ kh)
{
    const long n4 = (long)BATCH * CH * DD / 4;
    const long stride = (long)gridDim.x * blockDim.x;
    for (long i = (long)blockIdx.x * blockDim.x + threadIdx.x; i < n4; i += stride) {
        float4 v1 = ((const float4*)x1)[i];
        float4 v2 = ((const float4*)x2)[i];
        __half2 h1a = __floats2half2_rn(v1.x, v1.y), h1b = __floats2half2_rn(v1.z, v1.w);
        __half2 h2a = __floats2half2_rn(v2.x, v2.y), h2b = __floats2half2_rn(v2.z, v2.w);
        uint2 o1 = { *(unsigned*)&h1a, *(unsigned*)&h1b };
        uint2 o2 = { *(unsigned*)&h2a, *(unsigned*)&h2b };
        ((uint2*)qh)[i] = o1;
        ((uint2*)kh)[i] = o2;
    }
}

// ------------------- GEMM constants (R7 config: BK=32, 4 stages) -------------------
#define BK      32
#define ROWMK   80
#define ROWKN   272
#define NSTAGE  4
#define ATB0    (128 * ROWMK)   // 10240  (layout-0 tile)
#define ATB1    (BK * ROWKN)    // 8704   (layout-1 tile)

// Core GEMM device function. ALAY/BLAY as in prior rounds.
template<int ALAY, int BLAY>
__device__ __forceinline__ void gemm_core(
    const __half* __restrict__ A, const __half* __restrict__ B, float* __restrict__ C,
    int K, int lda, int ldb, int ldc, float scale,
    int m0, int n0, unsigned sb, int tid)
{
    constexpr int ATB = (ALAY == 0) ? ATB0 : ATB1;
    constexpr int BTB = (BLAY == 0) ? ATB0 : ATB1;
    constexpr int STG = ATB + BTB;

    const int wid = tid >> 5, lane = tid & 31;
    const int wm  = wid & 1, wn = wid >> 1;

    const __half* Ab = A + (ALAY == 0 ? (long)m0 * lda : (long)m0);
    const __half* Bb = B + (BLAY == 0 ? (long)n0 * ldb : (long)n0);

    auto load_tile = [&](const __half* G, int ld, int kt, unsigned dstBase, int lay) {
#pragma unroll
        for (int h = 0; h < 4; h++) {
            int i = tid + h * 128;
            if (lay == 0) {
                int row = i >> 2, c = i & 3;
                CPA16(dstBase + (unsigned)(row * ROWMK + c * 16),
                      (const char*)(G + (long)row * ld + kt * BK) + c * 16);
            } else {
                int row = i >> 4, c = i & 15;
                CPA16(dstBase + (unsigned)(row * ROWKN + c * 16),
                      (const char*)(G + (long)(kt * BK + row) * ld) + c * 16);
            }
        }
    };
    auto load_stage = [&](int kt, int s) {
        const unsigned base = sb + (unsigned)s * STG;
        load_tile(Ab, lda, kt, base, ALAY);
        load_tile(Bb, ldb, kt, base + ATB, BLAY);
    };

    unsigned a_off, b_off;
    if (ALAY == 0)
        a_off = (unsigned)((wm * 64 + (lane & 15)) * ROWMK + ((lane >> 4) & 1) * 16);
    else
        a_off = (unsigned)(((lane & 7) + ((lane >> 4) & 1) * 8) * ROWKN
                           + (wm * 64 + ((lane >> 3) & 1) * 8) * 2);
    if (BLAY == 0)
        b_off = (unsigned)(ATB + (wn * 64 + (lane & 7) + ((lane >> 4) & 1) * 8) * ROWMK
                           + ((lane >> 3) & 1) * 16);
    else
        b_off = (unsigned)(ATB + ((lane & 7) + ((lane >> 3) & 1) * 8) * ROWKN
                           + (wn * 64 + ((lane >> 4) & 1) * 8) * 2);

    float acc[4][8][4];
#pragma unroll
    for (int i = 0; i < 4; i++)
#pragma unroll
        for (int j = 0; j < 8; j++)
#pragma unroll
            for (int v = 0; v < 4; v++) acc[i][j][v] = 0.f;

    const int NT = K / BK;
    load_stage(0, 0); CPA_COMMIT();
    load_stage(1, 1); CPA_COMMIT();
    load_stage(2, 2); CPA_COMMIT();

    for (int kt = 0; kt < NT; kt++) {
        CPA_WAITG(2);
        __syncthreads();
        if (kt + 3 < NT) load_stage(kt + 3, (kt + 3) & (NSTAGE - 1));
        CPA_COMMIT();

        const unsigned stg = sb + (unsigned)(kt & (NSTAGE - 1)) * STG;
#pragma unroll
        for (int ks = 0; ks < 2; ks++) {
            unsigned af[4][4], bf[4][4];
#pragma unroll
            for (int mi = 0; mi < 4; mi++) {
                if (ALAY == 0)
                    LDSM_X4(af[mi], stg + a_off + (unsigned)(mi * 16 * ROWMK + ks * 32));
                else
                    LDSM_X4T(af[mi], stg + a_off + (unsigned)(ks * 16 * ROWKN + mi * 32));
            }
#pragma unroll
            for (int nt = 0; nt < 4; nt++) {
                if (BLAY == 0)
                    LDSM_X4(bf[nt], stg + b_off + (unsigned)(nt * 16 * ROWMK + ks * 32));
                else
                    LDSM_X4T(bf[nt], stg + b_off + (unsigned)(ks * 16 * ROWKN + nt * 32));
            }
#pragma unroll
            for (int mi = 0; mi < 4; mi++)
#pragma unroll
                for (int n8 = 0; n8 < 8; n8++) {
                    const unsigned* bp = bf[n8 >> 1];
                    mma16816(acc[mi][n8], af[mi],
                             bp[(n8 & 1) * 2], bp[(n8 & 1) * 2 + 1]);
                }
        }
    }

    float* Cb = C + (long)(m0 + wm * 64) * ldc + n0 + wn * 64;
    const int r0 = lane >> 2, c0 = (lane & 3) * 2;
#pragma unroll
    for (int mi = 0; mi < 4; mi++) {
#pragma unroll
        for (int n8 = 0; n8 < 8; n8++) {
            float* p = Cb + (long)(mi * 16 + r0) * ldc + n8 * 8 + c0;
            float2 v0 = { acc[mi][n8][0] * scale, acc[mi][n8][1] * scale };
            float2 v1 = { acc[mi][n8][2] * scale, acc[mi][n8][3] * scale };
            *(float2*)p = v0;
            *(float2*)(p + 8 * (long)ldc) = v1;
        }
    }
}

// ------------------- kernel 1: S = (1/64) q k^T -------------------
__global__ void __launch_bounds__(128, 2)
gemm1(const __half* __restrict__ qh, const __half* __restrict__ kh, float* __restrict__ S)
{
    extern __shared__ char smem[];
    const unsigned sb = smem_u32(smem);
    const int bz = blockIdx.z;
    gemm_core<0, 0>(qh + (long)bz * CH * DD, kh + (long)bz * CH * DD,
                    S + (long)bz * CH * CH,
                    DD, DD, DD, CH, 1.0f / 64.0f,
                    blockIdx.y * 128, blockIdx.x * 128, sb, threadIdx.x);
}

// ------------------- kernel 3: merged G2 (outA) + G3 (outB) -------------------
// z 0..15  : outA = Pa @ kh   (ALAY=0, BLAY=1)
// z 16..31 : outB = Mn^T @ qh (ALAY=1, BLAY=1)
__global__ void __launch_bounds__(128, 2)
gemm23(const __half* __restrict__ Pa, const __half* __restrict__ Mn,
       const __half* __restrict__ qh, const __half* __restrict__ kh,
       float* __restrict__ outA, float* __restrict__ outB)
{
    extern __shared__ char smem[];
    const unsigned sb = smem_u32(smem);
    const int z = blockIdx.z;
    if (z < BATCH) {
        gemm_core<0, 1>(Pa + (long)z * CH * CH, kh + (long)z * CH * DD,
                        outA + (long)z * CH * DD,
                        CH, CH, DD, DD, 1.0f,
                        blockIdx.y * 128, blockIdx.x * 128, sb, threadIdx.x);
    } else {
        const int b = z - BATCH;
        gemm_core<1, 1>(Mn + (long)b * CH * CH, qh + (long)b * CH * DD,
                        outB + (long)b * CH * DD,
                        CH, CH, DD, DD, 1.0f,
                        blockIdx.y * 128, blockIdx.x * 128, sb, threadIdx.x);
    }
}

// ------------------- merged softmax kernel -------------------
// blocks [0, 8192): row softmax, b = x>>9, r = x&511, 256 thr
// blocks [8192, 8320): col softmax, 64-wide e-tile, 4 c-groups of 128, 256 thr
__global__ void softmax_both(const float* __restrict__ S,
                             __half* __restrict__ Pa, __half* __restrict__ Mn)
{
    const int tid = threadIdx.x;   // 256
    if (blockIdx.x < 8192) {
        const int b = blockIdx.x >> 9, r = blockIdx.x & 511;
        const float* row = S + ((long)b * CH + r) * CH;
        __half* prow = Pa + ((long)b * CH + r) * CH;

        float v0 = row[tid], v1 = row[tid + 256];
        float m = fmaxf(v0, v1);
#pragma unroll
        for (int o = 16; o > 0; o >>= 1) m = fmaxf(m, __shfl_xor_sync(0xffffffffu, m, o));

        __shared__ float red[8];
        if ((tid & 31) == 0) red[tid >> 5] = m;
        __syncthreads();
        float mall = red[0];
#pragma unroll
        for (int w = 1; w < 8; w++) mall = fmaxf(mall, red[w]);

        float e0 = expf(v0 - mall), e1 = expf(v1 - mall);
        float s = e0 + e1;
#pragma unroll
        for (int o = 16; o > 0; o >>= 1) s += __shfl_xor_sync(0xffffffffu, s, o);
        __syncthreads();
        if ((tid & 31) == 0) red[tid >> 5] = s;
        __syncthreads();
        float sall = 0.f;
#pragma unroll
        for (int w = 0; w < 8; w++) sall += red[w];

        float inv = 1.0f / sall;
        prow[tid]       = __float2half_rn(e0 * inv);
        prow[tid + 256] = __float2half_rn(e1 * inv);
    } else {
        const int idx  = blockIdx.x - 8192;      // 0..127
        const int b    = idx >> 3;
        const int lane = tid & 63;
        const int g    = tid >> 6;               // c-group 0..3 (128 c each)
        const int e    = (idx & 7) * 64 + lane;

        const float* Sb = S + (long)b * CH * CH;
        __half* Mb = Mn + (long)b * CH * CH;

        float m = -INFINITY, s = 0.f;
        for (int c = g * 128; c < g * 128 + 128; c += 4) {
            float v0 = Sb[(long)(c + 0) * CH + e];
            float v1 = Sb[(long)(c + 1) * CH + e];
            float v2 = Sb[(long)(c + 2) * CH + e];
            float v3 = Sb[(long)(c + 3) * CH + e];
            float mn   = fmaxf(fmaxf(v0, v1), fmaxf(v2, v3));
            float mnew = fmaxf(m, mn);
            s = s * expf(m - mnew)
              + expf(v0 - mnew) + expf(v1 - mnew) + expf(v2 - mnew) + expf(v3 - mnew);
            m = mnew;
        }

        __shared__ float sm[4][64];
        __shared__ float ss[4][64];
        sm[g][lane] = m;
        ss[g][lane] = s;
        __syncthreads();

        float M = -INFINITY, Sv = 0.f;
#pragma unroll
        for (int gi = 0; gi < 4; gi++) {
            float mg = sm[gi][lane], sg = ss[gi][lane];
            float Mn2 = fmaxf(M, mg);
            Sv = Sv * expf(M - Mn2) + sg * expf(mg - Mn2);
            M = Mn2;
        }
        float inv = 1.0f / Sv;

        for (int c = g * 128; c < g * 128 + 128; c++) {
            Mb[(long)c * CH + e] = __float2half_rn(expf(Sb[(long)c * CH + e] - M) * inv);
        }
    }
}

// ------------------- launcher -------------------
extern "C" void kernel_launch(void* const* d_in, const int* in_sizes, int n_in,
                              void* d_out, int out_size)
{
    const float* x1 = (const float*)d_in[0];
    const float* x2 = (const float*)d_in[1];
    float* outA = (float*)d_out;
    float* outB = outA + (long)BATCH * CH * DD;

    __half *qh, *kh, *Pa, *Mn;
    float *S;
    cudaGetSymbolAddress((void**)&qh, g_qh);
    cudaGetSymbolAddress((void**)&kh, g_kh);
    cudaGetSymbolAddress((void**)&S,  g_S);
    cudaGetSymbolAddress((void**)&Pa, g_Pa);
    cudaGetSymbolAddress((void**)&Mn, g_Mn);

    constexpr int SM00 = NSTAGE * (ATB0 + ATB0);  // 81920
    constexpr int SM01 = NSTAGE * (ATB0 + ATB1);  // 75776 (covers both gemm23 paths)
    cudaFuncSetAttribute(gemm1,  cudaFuncAttributeMaxDynamicSharedMemorySize, SM00);
    cudaFuncSetAttribute(gemm23, cudaFuncAttributeMaxDynamicSharedMemorySize, SM01);

    // 0) fp32 -> fp16 cast
    convert_cast<<<8192, 256>>>(x1, x2, qh, kh);

    // 1) S = (1/64) * q @ k^T     M=512 N=512 K=4096
    gemm1<<<dim3(CH / 128, CH / 128, BATCH), 128, SM00>>>(qh, kh, S);

    // 2) both softmaxes, one launch
    softmax_both<<<8192 + 128, 256>>>(S, Pa, Mn);

    // 3+4) outA and outB, one launch
    gemm23<<<dim3(DD / 128, CH / 128, 2 * BATCH), 128, SM01>>>(Pa, Mn, qh, kh, outA, outB);
}

// round 11
// speedup vs baseline: 1.9189x; 1.3768x over previous
#include <cuda_runtime.h>
#include <cuda_fp16.h>
#include <stdint.h>
#include <math.h>

#define BATCH 16
#define CH    512
#define DD    4096

// ------------------- scratch (__device__ globals) -------------------
__device__ __half g_qh[BATCH * CH * DD];   // x1 fp16 [b][c][d]
__device__ __half g_kh[BATCH * CH * DD];   // x2 fp16 [b][e][d]
__device__ float  g_S [BATCH * CH * CH];   // scores fp32 [b][c][e]
__device__ __half g_Pa[BATCH * CH * CH];   // row softmax fp16 [b][c][e]
__device__ __half g_Mn[BATCH * CH * CH];   // col softmax fp16 [b][c][e]

// ------------------- helpers -------------------
__device__ __forceinline__ unsigned smem_u32(const void* p) {
    unsigned a;
    asm("{ .reg .u64 t; cvta.to.shared.u64 t, %1; cvt.u32.u64 %0, t; }" : "=r"(a) : "l"(p));
    return a;
}

#define CPA16(dst, src)  asm volatile("cp.async.cg.shared.global [%0], [%1], 16;" :: "r"(dst), "l"(src) : "memory")
#define CPA_COMMIT()     asm volatile("cp.async.commit_group;" ::: "memory")
#define CPA_WAITG(n)     asm volatile("cp.async.wait_group %0;" :: "n"(n) : "memory")

#define LDSM_X4(r, a) asm volatile(                                    \
    "ldmatrix.sync.aligned.m8n8.x4.shared.b16 {%0,%1,%2,%3}, [%4];"    \
    : "=r"((r)[0]), "=r"((r)[1]), "=r"((r)[2]), "=r"((r)[3]) : "r"(a))
#define LDSM_X4T(r, a) asm volatile(                                   \
    "ldmatrix.sync.aligned.m8n8.x4.trans.shared.b16 {%0,%1,%2,%3}, [%4];" \
    : "=r"((r)[0]), "=r"((r)[1]), "=r"((r)[2]), "=r"((r)[3]) : "r"(a))

__device__ __forceinline__ void mma16816(float* c, const unsigned* a,
                                         unsigned b0, unsigned b1) {
    asm volatile(
        "mma.sync.aligned.m16n8k16.row.col.f32.f16.f16.f32 "
        "{%0,%1,%2,%3}, {%4,%5,%6,%7}, {%8,%9}, {%0,%1,%2,%3};"
        : "+f"(c[0]), "+f"(c[1]), "+f"(c[2]), "+f"(c[3])
        : "r"(a[0]), "r"(a[1]), "r"(a[2]), "r"(a[3]), "r"(b0), "r"(b1));
}

// ------------------- fp32 -> fp16 cast, 4 iters fully unrolled, MLP=8 -------------------
// grid 8192 x 256: exactly 4 float4 per tensor per thread.
__global__ void __launch_bounds__(256)
convert_cast(const float* __restrict__ x1, const float* __restrict__ x2,
             __half* __restrict__ qh, __half* __restrict__ kh)
{
    const long base   = (long)blockIdx.x * 256 + threadIdx.x;
    const long stride = 8192L * 256;
    float4 v1[4], v2[4];
#pragma unroll
    for (int t = 0; t < 4; t++) {
        v1[t] = ((const float4*)x1)[base + t * stride];
        v2[t] = ((const float4*)x2)[base + t * stride];
    }
#pragma unroll
    for (int t = 0; t < 4; t++) {
        __half2 a0 = __floats2half2_rn(v1[t].x, v1[t].y), a1 = __floats2half2_rn(v1[t].z, v1[t].w);
        __half2 b0 = __floats2half2_rn(v2[t].x, v2[t].y), b1 = __floats2half2_rn(v2[t].z, v2[t].w);
        uint2 o1 = { *(unsigned*)&a0, *(unsigned*)&a1 };
        uint2 o2 = { *(unsigned*)&b0, *(unsigned*)&b1 };
        ((uint2*)qh)[base + t * stride] = o1;
        ((uint2*)kh)[base + t * stride] = o2;
    }
}

// ------------------- HMMA fp16 GEMM (R7 config, verbatim) -------------------
#define BK      32
#define ROWMK   80
#define ROWKN   272
#define NSTAGE  4

template<int LAY> struct TileBytes { static const int v = 128 * ROWMK; };  // 10240
template<> struct TileBytes<1>     { static const int v = BK * ROWKN;  };  // 8704

template<int ALAY, int BLAY>
__global__ void __launch_bounds__(128, 2)
gemm_mma(const __half* __restrict__ A, const __half* __restrict__ B, float* __restrict__ C,
         int K, int lda, int ldb, int ldc,
         long sA, long sB, long sC, float scale)
{
    constexpr int ATB = TileBytes<ALAY>::v;
    constexpr int BTB = TileBytes<BLAY>::v;
    constexpr int STG = ATB + BTB;

    extern __shared__ char smem[];
    const unsigned sb = smem_u32(smem);

    const int tid  = threadIdx.x;
    const int wid  = tid >> 5, lane = tid & 31;
    const int wm   = wid & 1, wn = wid >> 1;

    const int m0 = blockIdx.y * 128, n0 = blockIdx.x * 128;
    const __half* Ab = A + (long)blockIdx.z * sA + (ALAY == 0 ? (long)m0 * lda : (long)m0);
    const __half* Bb = B + (long)blockIdx.z * sB + (BLAY == 0 ? (long)n0 * ldb : (long)n0);

    auto load_tile = [&](const __half* G, int ld, int kt, unsigned dstBase, int lay) {
#pragma unroll
        for (int h = 0; h < 4; h++) {
            int i = tid + h * 128;
            if (lay == 0) {
                int row = i >> 2, c = i & 3;
                CPA16(dstBase + (unsigned)(row * ROWMK + c * 16),
                      (const char*)(G + (long)row * ld + kt * BK) + c * 16);
            } else {
                int row = i >> 4, c = i & 15;
                CPA16(dstBase + (unsigned)(row * ROWKN + c * 16),
                      (const char*)(G + (long)(kt * BK + row) * ld) + c * 16);
            }
        }
    };
    auto load_stage = [&](int kt, int s) {
        const unsigned base = sb + (unsigned)s * STG;
        load_tile(Ab, lda, kt, base, ALAY);
        load_tile(Bb, ldb, kt, base + ATB, BLAY);
    };

    unsigned a_off, b_off;
    if (ALAY == 0)
        a_off = (unsigned)((wm * 64 + (lane & 15)) * ROWMK + ((lane >> 4) & 1) * 16);
    else
        a_off = (unsigned)(((lane & 7) + ((lane >> 4) & 1) * 8) * ROWKN
                           + (wm * 64 + ((lane >> 3) & 1) * 8) * 2);
    if (BLAY == 0)
        b_off = (unsigned)(ATB + (wn * 64 + (lane & 7) + ((lane >> 4) & 1) * 8) * ROWMK
                           + ((lane >> 3) & 1) * 16);
    else
        b_off = (unsigned)(ATB + ((lane & 7) + ((lane >> 3) & 1) * 8) * ROWKN
                           + (wn * 64 + ((lane >> 4) & 1) * 8) * 2);

    float acc[4][8][4];
#pragma unroll
    for (int i = 0; i < 4; i++)
#pragma unroll
        for (int j = 0; j < 8; j++)
#pragma unroll
            for (int v = 0; v < 4; v++) acc[i][j][v] = 0.f;

    const int NT = K / BK;
    load_stage(0, 0); CPA_COMMIT();
    load_stage(1, 1); CPA_COMMIT();
    load_stage(2, 2); CPA_COMMIT();

    for (int kt = 0; kt < NT; kt++) {
        CPA_WAITG(2);
        __syncthreads();
        if (kt + 3 < NT) load_stage(kt + 3, (kt + 3) & (NSTAGE - 1));
        CPA_COMMIT();

        const unsigned stg = sb + (unsigned)(kt & (NSTAGE - 1)) * STG;
#pragma unroll
        for (int ks = 0; ks < 2; ks++) {
            unsigned af[4][4], bf[4][4];
#pragma unroll
            for (int mi = 0; mi < 4; mi++) {
                if (ALAY == 0)
                    LDSM_X4(af[mi], stg + a_off + (unsigned)(mi * 16 * ROWMK + ks * 32));
                else
                    LDSM_X4T(af[mi], stg + a_off + (unsigned)(ks * 16 * ROWKN + mi * 32));
            }
#pragma unroll
            for (int nt = 0; nt < 4; nt++) {
                if (BLAY == 0)
                    LDSM_X4(bf[nt], stg + b_off + (unsigned)(nt * 16 * ROWMK + ks * 32));
                else
                    LDSM_X4T(bf[nt], stg + b_off + (unsigned)(ks * 16 * ROWKN + nt * 32));
            }
#pragma unroll
            for (int mi = 0; mi < 4; mi++)
#pragma unroll
                for (int n8 = 0; n8 < 8; n8++) {
                    const unsigned* bp = bf[n8 >> 1];
                    mma16816(acc[mi][n8], af[mi],
                             bp[(n8 & 1) * 2], bp[(n8 & 1) * 2 + 1]);
                }
        }
    }

    float* Cb = C + (long)blockIdx.z * sC
                  + (long)(m0 + wm * 64) * ldc + n0 + wn * 64;
    const int r0 = lane >> 2, c0 = (lane & 3) * 2;
#pragma unroll
    for (int mi = 0; mi < 4; mi++) {
#pragma unroll
        for (int n8 = 0; n8 < 8; n8++) {
            float* p = Cb + (long)(mi * 16 + r0) * ldc + n8 * 8 + c0;
            float2 v0 = { acc[mi][n8][0] * scale, acc[mi][n8][1] * scale };
            float2 v1 = { acc[mi][n8][2] * scale, acc[mi][n8][3] * scale };
            *(float2*)p = v0;
            *(float2*)(p + 8 * (long)ldc) = v1;
        }
    }
}

// ------------------- merged softmax: col blocks FIRST, 512 thr both roles -------------------
// blocks [0, 128):    col softmax (R7 config: 64-wide e-tile, 8 c-groups of 64)
// blocks [128, 8320): row softmax (512 thr, 1 elem/thread)
__global__ void __launch_bounds__(512)
softmax_all(const float* __restrict__ S, __half* __restrict__ Pa, __half* __restrict__ Mn)
{
    const int tid = threadIdx.x;   // 512
    if (blockIdx.x < 128) {
        // ---- col softmax (identical to R7 col_softmax_k) ----
        const int idx  = blockIdx.x;
        const int b    = idx >> 3;
        const int lane = tid & 63;
        const int g    = tid >> 6;               // c-group 0..7
        const int e    = (idx & 7) * 64 + lane;

        const float* Sb = S + (long)b * CH * CH;
        __half* Mb = Mn + (long)b * CH * CH;

        float m = -INFINITY, s = 0.f;
        for (int c = g * 64; c < g * 64 + 64; c += 4) {
            float v0 = Sb[(long)(c + 0) * CH + e];
            float v1 = Sb[(long)(c + 1) * CH + e];
            float v2 = Sb[(long)(c + 2) * CH + e];
            float v3 = Sb[(long)(c + 3) * CH + e];
            float mn   = fmaxf(fmaxf(v0, v1), fmaxf(v2, v3));
            float mnew = fmaxf(m, mn);
            s = s * expf(m - mnew)
              + expf(v0 - mnew) + expf(v1 - mnew) + expf(v2 - mnew) + expf(v3 - mnew);
            m = mnew;
        }

        __shared__ float sm[8][64];
        __shared__ float ss[8][64];
        sm[g][lane] = m;
        ss[g][lane] = s;
        __syncthreads();

        float M = -INFINITY, Sv = 0.f;
#pragma unroll
        for (int gi = 0; gi < 8; gi++) {
            float mg = sm[gi][lane], sg = ss[gi][lane];
            float Mn2 = fmaxf(M, mg);
            Sv = Sv * expf(M - Mn2) + sg * expf(mg - Mn2);
            M = Mn2;
        }
        float inv = 1.0f / Sv;

        for (int c = g * 64; c < g * 64 + 64; c++) {
            Mb[(long)c * CH + e] = __float2half_rn(expf(Sb[(long)c * CH + e] - M) * inv);
        }
    } else {
        // ---- row softmax, 1 element per thread ----
        const int idx = blockIdx.x - 128;
        const int b = idx >> 9, r = idx & 511;
        const float* row = S + ((long)b * CH + r) * CH;
        __half* prow = Pa + ((long)b * CH + r) * CH;

        float v = row[tid];
        float m = v;
#pragma unroll
        for (int o = 16; o > 0; o >>= 1) m = fmaxf(m, __shfl_xor_sync(0xffffffffu, m, o));

        __shared__ float red[16];
        if ((tid & 31) == 0) red[tid >> 5] = m;
        __syncthreads();
        float mall = red[0];
#pragma unroll
        for (int w = 1; w < 16; w++) mall = fmaxf(mall, red[w]);

        float e = expf(v - mall);
        float s = e;
#pragma unroll
        for (int o = 16; o > 0; o >>= 1) s += __shfl_xor_sync(0xffffffffu, s, o);
        __syncthreads();
        if ((tid & 31) == 0) red[tid >> 5] = s;
        __syncthreads();
        float sall = 0.f;
#pragma unroll
        for (int w = 0; w < 16; w++) sall += red[w];

        prow[tid] = __float2half_rn(e / sall);
    }
}

// ------------------- launcher -------------------
extern "C" void kernel_launch(void* const* d_in, const int* in_sizes, int n_in,
                              void* d_out, int out_size)
{
    const float* x1 = (const float*)d_in[0];
    const float* x2 = (const float*)d_in[1];
    float* outA = (float*)d_out;
    float* outB = outA + (long)BATCH * CH * DD;

    __half *qh, *kh, *Pa, *Mn;
    float *S;
    cudaGetSymbolAddress((void**)&qh, g_qh);
    cudaGetSymbolAddress((void**)&kh, g_kh);
    cudaGetSymbolAddress((void**)&S,  g_S);
    cudaGetSymbolAddress((void**)&Pa, g_Pa);
    cudaGetSymbolAddress((void**)&Mn, g_Mn);

    constexpr int SM00 = NSTAGE * (TileBytes<0>::v + TileBytes<0>::v);  // 81920
    constexpr int SM01 = NSTAGE * (TileBytes<0>::v + TileBytes<1>::v);  // 75776
    constexpr int SM11 = NSTAGE * (TileBytes<1>::v + TileBytes<1>::v);  // 69632
    cudaFuncSetAttribute(gemm_mma<0, 0>, cudaFuncAttributeMaxDynamicSharedMemorySize, SM00);
    cudaFuncSetAttribute(gemm_mma<0, 1>, cudaFuncAttributeMaxDynamicSharedMemorySize, SM01);
    cudaFuncSetAttribute(gemm_mma<1, 1>, cudaFuncAttributeMaxDynamicSharedMemorySize, SM11);

    // 0) fp32 -> fp16 cast
    convert_cast<<<8192, 256>>>(x1, x2, qh, kh);

    // 1) S = (1/64) * q @ k^T     M=512 N=512 K=4096
    gemm_mma<0, 0><<<dim3(CH / 128, CH / 128, BATCH), 128, SM00>>>(
        qh, kh, S, DD, DD, DD, CH,
        (long)CH * DD, (long)CH * DD, (long)CH * CH, 1.0f / 64.0f);

    // 2) both softmaxes, one launch, col blocks first
    softmax_all<<<128 + 8192, 512>>>(S, Pa, Mn);

    // 3) outA = Pa @ k            M=512 N=4096 K=512
    gemm_mma<0, 1><<<dim3(DD / 128, CH / 128, BATCH), 128, SM01>>>(
        Pa, kh, outA, CH, CH, DD, DD,
        (long)CH * CH, (long)CH * DD, (long)CH * DD, 1.0f);

    // 4) outB = Mn^T @ q          M=512(e) N=4096(d) K=512(c)
    gemm_mma<1, 1><<<dim3(DD / 128, CH / 128, BATCH), 128, SM11>>>(
        Mn, qh, outB, CH, CH, DD, DD,
        (long)CH * CH, (long)CH * DD, (long)CH * DD, 1.0f);
}